// round 7
// baseline (speedup 1.0000x reference)
#include <cuda_runtime.h>
#include <cstdint>

#define Bn 256
#define Tn 1024
#define Cn 256
#define Ln 128
#define NPER 256          // 256 periods x 4 steps: t = 4p+1 .. 4p+4 (last guarded)
#define RING 12
#define NEGF (-1e30f)
#define EPSF (1e-7f)
#define NTH 224           // 7 warps
#define LN2F 0.6931471805599453f

// grid = 128 blocks; block processes batch rows 2*blockIdx.x and +1.
// Roles (one rec warp per SMSP):
//   tid   0..127 : recurrence for BOTH rows; thread k owns states 2k,2k+1 per row;
//                  K=4 steps/barrier, 9-state halo, linear-in-period (R5 scheme).
//   tid 128..159 : per-row denominator sums + blank-emission capture (8 rows/period)
//   tid 160..223 : cp.async loaders (64 x 16B), 8 time-rows/period (4 per batch row)
// State 256 excluded from recurrence; reconstructed in epilogue (validated R4/R5).

__device__ __forceinline__ float ex2f(float x){ float r; asm("ex2.approx.ftz.f32 %0, %1;" : "=f"(r) : "f"(x)); return r; }
__device__ __forceinline__ float lg2f(float x){ float r; asm("lg2.approx.ftz.f32 %0, %1;" : "=f"(r) : "f"(x)); return r; }

extern __shared__ __align__(16) float smemf[];

// dynamic smem layout (floats):
//   ring   : [2][RING][Cn]          = 6144
//   abuf   : [2][2][264]            = 1056
//   sums   : [2][Tn]                = 2048
//   vbh    : [2][Tn]                = 2048
//   histL  : [2][Tn]                = 2048
//   histM  : [2][NPER]              = 512
//   pre    : [2][Tn]                = 2048
//   csum   : [128], coff : [128]    = 256   (reused per row)
//   labs   : [2][132] (as int)      = 264
//   wredA/B/C : [8]*3               = 24
//   PtotS, flag64                   = 2
#define OFF_RING  0
#define OFF_ABUF  (OFF_RING + 2*RING*Cn)
#define OFF_SUMS  (OFF_ABUF + 2*2*264)
#define OFF_VBH   (OFF_SUMS + 2*Tn)
#define OFF_HISTL (OFF_VBH + 2*Tn)
#define OFF_HISTM (OFF_HISTL + 2*Tn)
#define OFF_PRE   (OFF_HISTM + 2*NPER)
#define OFF_CSUM  (OFF_PRE + 2*Tn)
#define OFF_COFF  (OFF_CSUM + 128)
#define OFF_LABS  (OFF_COFF + 128)
#define OFF_WREDA (OFF_LABS + 2*132)
#define OFF_WREDB (OFF_WREDA + 8)
#define OFF_WREDC (OFF_WREDB + 8)
#define OFF_PTOT  (OFF_WREDC + 8)
#define OFF_F64   (OFF_PTOT + 1)
#define SMEM_FLOATS (OFF_F64 + 1)

__global__ __launch_bounds__(NTH)
void ctc_kernel(const void* __restrict__ yt_raw,
                const float* __restrict__ yp,
                float* __restrict__ out)
{
    float* ring  = smemf + OFF_RING;       // ring[(r*RING+sl)*Cn + c]
    float* abuf  = smemf + OFF_ABUF;       // abuf[((r*2)+buf)*264 + i]
    float* sums  = smemf + OFF_SUMS;
    float* vbh   = smemf + OFF_VBH;
    float* histL = smemf + OFF_HISTL;
    float* histM = smemf + OFF_HISTM;
    float* pre   = smemf + OFF_PRE;
    float* csum  = smemf + OFF_CSUM;
    float* coff  = smemf + OFF_COFF;
    int*   labs  = (int*)(smemf + OFF_LABS);   // labs[r*132 + i]
    float* wredA = smemf + OFF_WREDA;
    float* wredB = smemf + OFF_WREDB;
    float* wredC = smemf + OFF_WREDC;
    float* PtotS = smemf + OFF_PTOT;
    int*   flag64 = (int*)(smemf + OFF_F64);

    const int b0  = 2 * blockIdx.x;
    const int tid = threadIdx.x;

    if (tid == 0) *flag64 = 1;

    // prologue: rows 0..8 for both batch rows
    if (tid >= 160) {
        const int lt = tid - 160;
        #pragma unroll
        for (int r = 0; r < 2; ++r) {
            const float* rb = yp + (size_t)(b0 + r) * Tn * Cn;
            #pragma unroll
            for (int rr = 0; rr < 9; ++rr) {
                unsigned sa = (unsigned)__cvta_generic_to_shared(&ring[(r*RING + rr)*Cn + lt*4]);
                const float* g = rb + (size_t)rr * Cn + lt * 4;
                asm volatile("cp.async.cg.shared.global [%0], [%1], 16;\n" :: "r"(sa), "l"(g));
            }
        }
        asm volatile("cp.async.commit_group;\n");
    }
    __syncthreads();

    if (tid < 128) { if (((const int*)yt_raw)[2 * tid + 1] != 0) *flag64 = 0; }
    __syncthreads();

    const int f64 = *flag64;
    if (tid < 160) {                 // 160 threads load 2x128 labels + pads
        #pragma unroll
        for (int r = 0; r < 2; ++r) {
            for (int i = tid; i < 132; i += 160) {
                int v = Cn - 1;
                if (i < Ln) v = f64 ? (int)((const long long*)yt_raw)[(size_t)(b0+r)*Ln + i]
                                    : ((const int*)yt_raw)[(size_t)(b0+r)*Ln + i];
                labs[r*132 + i] = v;
            }
        }
    }
    if (tid >= 160 && tid < 176) {   // NEG pads of abuf (i=0..7 all 4 buffers)
        const int q = tid - 160;     // 0..15 -> (rb, i)
        abuf[(q >> 3) * 2 * 264 + (q & 7)] = NEGF;
        abuf[((q >> 3) * 2 + 1) * 264 + (q & 7)] = NEGF;
    }
    if (tid >= 200) asm volatile("cp.async.wait_group 0;\n");  // subset ok; barrier covers rest
    if (tid >= 160 && tid < 200) asm volatile("cp.async.wait_group 0;\n");
    __syncthreads();

    // per-thread metadata per row: window idx 3,5,7,9 = labels k-3..k
    const int k = tid;
    int vo[2][4]; float sk[2][4];
    if (tid < 128) {
        #pragma unroll
        for (int r = 0; r < 2; ++r) {
            const int* lb = &labs[r*132];
            vo[r][3] = lb[k];
            sk[r][3] = (k >= 1 && lb[k] != lb[k-1]) ? 1.f : 0.f;
            vo[r][2] = (k >= 1) ? lb[k-1] : Cn-1;
            sk[r][2] = (k >= 2 && lb[k-1] != lb[k-2]) ? 1.f : 0.f;
            vo[r][1] = (k >= 2) ? lb[k-2] : Cn-1;
            sk[r][1] = (k >= 3 && lb[k-2] != lb[k-3]) ? 1.f : 0.f;
            vo[r][0] = (k >= 3) ? lb[k-3] : Cn-1;
            sk[r][0] = (k >= 4 && lb[k-3] != lb[k-4]) ? 1.f : 0.f;
        }
    }

    // t = 0 init (log2 domain)
    if (tid < 128) {
        #pragma unroll
        for (int r = 0; r < 2; ++r) {
            float a0 = NEGF, a1 = NEGF;
            if (k == 0) {
                const float* r0 = &ring[(r*RING + 0)*Cn];
                a0 = lg2f(r0[Cn - 1] + EPSF);
                a1 = lg2f(r0[labs[r*132]] + EPSF);
            }
            float2 w = { a0, a1 };
            *(float2*)&abuf[(r*2 + 0)*264 + 8 + 2*k] = w;
        }
    }
    if (tid >= 128 && tid < 160) {
        const int l = tid - 128;
        #pragma unroll
        for (int r = 0; r < 2; ++r) {
            const float4* r4 = (const float4*)&ring[(r*RING)*Cn];
            float4 x = r4[l], y = r4[l + 32];
            float part = ((x.x + x.y) + (x.z + x.w)) + ((y.x + y.y) + (y.z + y.w));
            #pragma unroll
            for (int o = 16; o; o >>= 1) part += __shfl_xor_sync(0xffffffffu, part, o);
            if (l == 0) sums[r*Tn] = part + (float)Cn * EPSF;
        }
    }
    __syncthreads();

    // ---- main loop: 256 periods x 4 steps x 2 rows ----
    int cur = 0;
    int s0 = 1;                            // (4p+1) % 12
    for (int p = 0; p < NPER; ++p) {
        if (tid < 128) {
            float A[2][10];
            #pragma unroll
            for (int r = 0; r < 2; ++r) {
                const float2* hp = (const float2*)&abuf[(r*2 + cur)*264 + 2*k];
                float2 h0 = hp[0], h1 = hp[1], h2 = hp[2], h3 = hp[3], h4 = hp[4];
                const float m = fmaxf(fmaxf(fmaxf(h0.y, h1.x), fmaxf(h1.y, h2.x)),
                                      fmaxf(fmaxf(h2.y, h3.x), fmaxf(h3.y, fmaxf(h4.x, h4.y))));
                A[r][1] = ex2f(h0.y - m); A[r][2] = ex2f(h1.x - m);
                A[r][3] = ex2f(h1.y - m); A[r][4] = ex2f(h2.x - m);
                A[r][5] = ex2f(h2.y - m); A[r][6] = ex2f(h3.x - m);
                A[r][7] = ex2f(h3.y - m); A[r][8] = ex2f(h4.x - m);
                A[r][9] = ex2f(h4.y - m);
                if (k == 127) histM[r*NPER + p] = m;
                A[r][0] = m;   // stash shift
            }
            #pragma unroll
            for (int jj = 0; jj < 4; ++jj) {
                if (4 * p + 1 + jj < Tn) {
                    int sl = s0 + jj; if (sl >= RING) sl -= RING;
                    #pragma unroll
                    for (int r = 0; r < 2; ++r) {
                        const float* rg = &ring[(r*RING + sl)*Cn];
                        const float vb = rg[Cn - 1] + EPSF;
                        {
                            const float v9 = rg[vo[r][3]] + EPSF;
                            A[r][9] = fmaf(sk[r][3], A[r][7], A[r][9] + A[r][8]) * v9;
                            A[r][8] = (A[r][8] + A[r][7]) * vb;
                        }
                        if (jj <= 2) { const float v7 = rg[vo[r][2]] + EPSF;
                                       A[r][7] = fmaf(sk[r][2], A[r][5], A[r][7] + A[r][6]) * v7;
                                       A[r][6] = (A[r][6] + A[r][5]) * vb; }
                        if (jj <= 1) { const float v5 = rg[vo[r][1]] + EPSF;
                                       A[r][5] = fmaf(sk[r][1], A[r][3], A[r][5] + A[r][4]) * v5;
                                       A[r][4] = (A[r][4] + A[r][3]) * vb; }
                        if (jj == 0) { const float v3 = rg[vo[r][0]] + EPSF;
                                       A[r][3] = fmaf(sk[r][0], A[r][1], A[r][3] + A[r][2]) * v3;
                                       A[r][2] = (A[r][2] + A[r][1]) * vb; }
                        if (k == 127) histL[r*Tn + 4*p + 1 + jj] = A[r][9];
                    }
                }
            }
            #pragma unroll
            for (int r = 0; r < 2; ++r) {
                const float m = A[r][0];
                const float L8 = fmaxf(m + lg2f(A[r][8]), NEGF);
                const float L9 = fmaxf(m + lg2f(A[r][9]), NEGF);
                float2 w = { L8, L9 };
                *(float2*)&abuf[(r*2 + (cur ^ 1))*264 + 8 + 2*k] = w;
            }
        }
        else if (tid < 160) {              // denominator sums + blank capture, 8 rows
            const int l = tid - 128;
            float pr[2][4];
            #pragma unroll
            for (int r = 0; r < 2; ++r) {
                #pragma unroll
                for (int rr = 0; rr < 4; ++rr) {
                    const int t = 4 * p + 1 + rr;
                    if (t < Tn) {
                        int sl = s0 + rr; if (sl >= RING) sl -= RING;
                        const float4* r4 = (const float4*)&ring[(r*RING + sl)*Cn];
                        float4 x = r4[l], y = r4[l + 32];
                        pr[r][rr] = ((x.x + x.y) + (x.z + x.w)) + ((y.x + y.y) + (y.z + y.w));
                        if (l == 31) vbh[r*Tn + t] = y.w;
                    } else pr[r][rr] = 0.f;
                }
            }
            #pragma unroll
            for (int o = 16; o; o >>= 1) {
                #pragma unroll
                for (int r = 0; r < 2; ++r) {
                    pr[r][0] += __shfl_xor_sync(0xffffffffu, pr[r][0], o);
                    pr[r][1] += __shfl_xor_sync(0xffffffffu, pr[r][1], o);
                    pr[r][2] += __shfl_xor_sync(0xffffffffu, pr[r][2], o);
                    pr[r][3] += __shfl_xor_sync(0xffffffffu, pr[r][3], o);
                }
            }
            if (l == 0) {
                #pragma unroll
                for (int r = 0; r < 2; ++r)
                    #pragma unroll
                    for (int rr = 0; rr < 4; ++rr) {
                        const int t = 4 * p + 1 + rr;
                        if (t < Tn) sums[r*Tn + t] = pr[r][rr] + (float)Cn * EPSF;
                    }
            }
        }
        else {                             // loaders: rows 4p+9 .. 4p+12, both batch rows
            const int lt = tid - 160;
            int sw = s0 + 8; if (sw >= RING) sw -= RING;
            #pragma unroll
            for (int r = 0; r < 2; ++r) {
                const float* rb = yp + (size_t)(b0 + r) * Tn * Cn;
                #pragma unroll
                for (int rr = 0; rr < 4; ++rr) {
                    const int rt = 4 * p + 9 + rr;
                    if (rt < Tn) {
                        int sl = sw + rr; if (sl >= RING) sl -= RING;
                        unsigned sa = (unsigned)__cvta_generic_to_shared(&ring[(r*RING + sl)*Cn + lt*4]);
                        const float* g = rb + (size_t)rt * Cn + lt * 4;
                        asm volatile("cp.async.cg.shared.global [%0], [%1], 16;\n" :: "r"(sa), "l"(g));
                    }
                }
            }
            asm volatile("cp.async.commit_group;\n");
            asm volatile("cp.async.wait_group 1;\n");
        }
        __syncthreads();
        cur ^= 1;
        s0 += 4; if (s0 >= RING) s0 -= RING;
    }

    // ==== epilogue: per batch row (scratch csum/coff/wred reused; synced) ====
    for (int r = 0; r < 2; ++r) {
        if (tid < 128) {
            const int base = 8 * tid;
            float rr = 0.f;
            #pragma unroll
            for (int j = 0; j < 8; ++j) {
                const int u = base + j;
                float x = (u == 0) ? 0.f : lg2f(vbh[r*Tn + u] + EPSF);
                rr += x;
                pre[r*Tn + u] = rr;
            }
            csum[tid] = rr;
        }
        __syncthreads();

        if (tid < 32) {
            float c0 = csum[4*tid], c1 = csum[4*tid+1], c2 = csum[4*tid+2], c3 = csum[4*tid+3];
            float tot = ((c0 + c1) + (c2 + c3));
            float sc = tot;
            #pragma unroll
            for (int o = 1; o < 32; o <<= 1) {
                float v = __shfl_up_sync(0xffffffffu, sc, o);
                if (tid >= o) sc += v;
            }
            const float ex = sc - tot;
            coff[4*tid]   = ex;
            coff[4*tid+1] = ex + c0;
            coff[4*tid+2] = ex + c0 + c1;
            coff[4*tid+3] = ex + c0 + c1 + c2;
            if (tid == 31) *PtotS = sc;
        }
        __syncthreads();

        const float Ptot = *PtotS;
        float lm = -3.0e38f;
        for (int u = tid; u < Tn - 1; u += NTH) {
            const float h = (u == 0) ? NEGF
                          : histM[r*NPER + ((u - 1) >> 2)] + lg2f(histL[r*Tn + u]);
            lm = fmaxf(lm, h + (Ptot - (coff[u >> 3] + pre[r*Tn + u])));
        }
        float d2 = 0.f;
        for (int t2 = tid; t2 < Tn; t2 += NTH) d2 += lg2f(sums[r*Tn + t2]);
        #pragma unroll
        for (int o = 16; o; o >>= 1) {
            lm = fmaxf(lm, __shfl_xor_sync(0xffffffffu, lm, o));
            d2 += __shfl_xor_sync(0xffffffffu, d2, o);
        }
        if ((tid & 31) == 0) { wredA[tid >> 5] = lm; wredB[tid >> 5] = d2; }
        __syncthreads();

        float M = wredA[0];
        #pragma unroll
        for (int w = 1; w < 7; ++w) M = fmaxf(M, wredA[w]);

        float se = 0.f;
        for (int u = tid; u < Tn - 1; u += NTH) {
            const float h = (u == 0) ? NEGF
                          : histM[r*NPER + ((u - 1) >> 2)] + lg2f(histL[r*Tn + u]);
            se += ex2f(h + (Ptot - (coff[u >> 3] + pre[r*Tn + u])) - M);
        }
        #pragma unroll
        for (int o = 16; o; o >>= 1) se += __shfl_xor_sync(0xffffffffu, se, o);
        if ((tid & 31) == 0) wredC[tid >> 5] = se;
        __syncthreads();

        if (tid == 0) {
            float S = 0.f, D2 = 0.f;
            #pragma unroll
            for (int w = 0; w < 7; ++w) { S += wredC[w]; D2 += wredB[w]; }
            const float a256 = M + lg2f(S);
            const float x = abuf[(r*2 + cur)*264 + 8 + 255];   // A255(T-1), base-2
            const float m2 = fmaxf(x, a256);
            const float lse2 = m2 + lg2f(ex2f(x - m2) + ex2f(a256 - m2));
            out[b0 + r] = LN2F * (D2 - lse2);
        }
        __syncthreads();
    }
}

extern "C" void kernel_launch(void* const* d_in, const int* in_sizes, int n_in,
                              void* d_out, int out_size)
{
    int iy = (in_sizes[0] == Bn * Ln) ? 0 : 1;
    const void*  yt = d_in[iy];
    const float* yp = (const float*)d_in[1 - iy];
    const size_t smem = SMEM_FLOATS * sizeof(float);
    cudaFuncSetAttribute(ctc_kernel, cudaFuncAttributeMaxDynamicSharedMemorySize, (int)smem);
    ctc_kernel<<<Bn / 2, NTH, smem>>>(yt, yp, (float*)d_out);
}

// round 8
// speedup vs baseline: 1.3603x; 1.3603x over previous
#include <cuda_runtime.h>
#include <cstdint>

#define Bn 256
#define Tn 1024
#define Cn 256
#define Ln 128
#define NPER 128          // 128 periods x 8 steps: t = 8p+1 .. 8p+8 (last guarded)
#define RING 24
#define NEGF (-1e30f)
#define EPSF (1e-7f)
#define NTH 256           // 8 warps
#define LN2F 0.6931471805599453f

// Roles:
//   tid   0..127 : recurrence warps 0-3 (one per SMSP); thread k owns states 2k,2k+1;
//                  K=8 steps per barrier, 17-state live halo, linear-in-period (R5 math).
//   tid 128..191 : loader warps 4,5; 64 threads x 16B chunks; 8 rows/period
//   tid 192..255 : sums warps 6,7; per-row denominator + blank-emission capture (4 rows each)
// State 256 excluded from recurrence; reconstructed in epilogue (validated R4/R5).

__device__ __forceinline__ float ex2f(float x){ float r; asm("ex2.approx.ftz.f32 %0, %1;" : "=f"(r) : "f"(x)); return r; }
__device__ __forceinline__ float lg2f(float x){ float r; asm("lg2.approx.ftz.f32 %0, %1;" : "=f"(r) : "f"(x)); return r; }

__global__ __launch_bounds__(NTH, 2)
void ctc_kernel(const void* __restrict__ yt_raw,
                const float* __restrict__ yp,
                float* __restrict__ out)
{
    __shared__ __align__(16) float ring[RING][Cn];   // 24KB row ring
    __shared__ __align__(8)  float abuf[2][292];     // state s at [16+s]; [0..15] NEG pad
    __shared__ float sums[Tn];
    __shared__ float vbh[Tn];                        // row[t][255] raw
    __shared__ float histL[Tn];                      // A255(t) linear-in-period
    __shared__ float histM[NPER];                    // per-period shift of thread 127
    __shared__ float pre[Tn];
    __shared__ float csum[128], coff[128];
    __shared__ int   labs[136];
    __shared__ float wredA[8], wredB[8], wredC[8];
    __shared__ float PtotS;
    __shared__ int   flag64;

    const int b   = blockIdx.x;
    const int tid = threadIdx.x;
    const float* rowbase = yp + (size_t)b * Tn * Cn;

    if (tid == 0) flag64 = 1;

    // prologue: rows 0..16 (init row + periods 0,1) in two groups
    if (tid >= 128 && tid < 192) {
        const int lt = tid - 128;
        #pragma unroll
        for (int r = 0; r < 9; ++r) {
            unsigned sa = (unsigned)__cvta_generic_to_shared(&ring[r][lt * 4]);
            const float* g = rowbase + (size_t)r * Cn + lt * 4;
            asm volatile("cp.async.cg.shared.global [%0], [%1], 16;\n" :: "r"(sa), "l"(g));
        }
        asm volatile("cp.async.commit_group;\n");
        #pragma unroll
        for (int r = 9; r < 17; ++r) {
            unsigned sa = (unsigned)__cvta_generic_to_shared(&ring[r][lt * 4]);
            const float* g = rowbase + (size_t)r * Cn + lt * 4;
            asm volatile("cp.async.cg.shared.global [%0], [%1], 16;\n" :: "r"(sa), "l"(g));
        }
        asm volatile("cp.async.commit_group;\n");
    }
    __syncthreads();

    if (tid < 128) { if (((const int*)yt_raw)[2 * tid + 1] != 0) flag64 = 0; }
    __syncthreads();

    if (tid < Ln) {
        labs[tid] = flag64 ? (int)((const long long*)yt_raw)[(size_t)b * Ln + tid]
                           : ((const int*)yt_raw)[(size_t)b * Ln + tid];
    }
    if (tid >= Ln && tid < 136) labs[tid] = Cn - 1;
    if (tid >= 192 && tid < 224) {       // NEG pads [0..15] of both buffers
        const int q = tid - 192;         // 0..31
        abuf[q >> 4][q & 15] = NEGF;
    }
    if (tid >= 128 && tid < 192) asm volatile("cp.async.wait_group 0;\n");
    __syncthreads();

    // metadata: pairs q=1..8 -> idx (2q+1, 2q), states (2k-16+2q+1, ...); odd = label k-8+q
    const int k = tid;
    int vo[8]; float sk[8];
    if (tid < 128) {
        #pragma unroll
        for (int q = 1; q <= 8; ++q) {
            const int i = k - 8 + q;
            vo[q-1] = (i >= 0) ? labs[i] : (Cn - 1);
            sk[q-1] = (i >= 1 && labs[i] != labs[i-1]) ? 1.f : 0.f;
        }
    }

    // t = 0 init (log2 domain)
    if (tid < 128) {
        float a0 = NEGF, a1 = NEGF;
        if (k == 0) {
            a0 = lg2f(ring[0][Cn - 1] + EPSF);
            a1 = lg2f(ring[0][labs[0]] + EPSF);
        }
        float2 w = { a0, a1 };
        *(float2*)&abuf[0][16 + 2 * k] = w;
    }
    if (tid >= 192 && tid < 224) {       // row-0 denominator (warp 6)
        const int l = tid - 192;
        const float4* r4 = (const float4*)ring[0];
        float4 x = r4[l], y = r4[l + 32];
        float part = ((x.x + x.y) + (x.z + x.w)) + ((y.x + y.y) + (y.z + y.w));
        #pragma unroll
        for (int o = 16; o; o >>= 1) part += __shfl_xor_sync(0xffffffffu, part, o);
        if (l == 0) sums[0] = part + (float)Cn * EPSF;
    }
    __syncthreads();

    // ---- main loop: 128 periods x 8 steps ----
    int cur = 0;
    int s0 = 1;                            // (8p+1) % 24
    for (int p = 0; p < NPER; ++p) {
        if (tid < 128) {
            const float2* hp = (const float2*)&abuf[cur][2 * k];  // states 2k-16 .. 2k+1
            float A[18];
            float2 h0 = hp[0], h1 = hp[1], h2 = hp[2], h3 = hp[3], h4 = hp[4],
                   h5 = hp[5], h6 = hp[6], h7 = hp[7], h8 = hp[8];
            // A[0] (state 2k-16) is never read by any update; skip it.
            const float m =
                fmaxf(fmaxf(fmaxf(fmaxf(h0.y, h1.x), fmaxf(h1.y, h2.x)),
                            fmaxf(fmaxf(h2.y, h3.x), fmaxf(h3.y, h4.x))),
                      fmaxf(fmaxf(fmaxf(h4.y, h5.x), fmaxf(h5.y, h6.x)),
                            fmaxf(fmaxf(h6.y, h7.x), fmaxf(h7.y, fmaxf(h8.x, h8.y)))));
            A[1] = ex2f(h0.y - m);  A[2] = ex2f(h1.x - m);  A[3] = ex2f(h1.y - m);
            A[4] = ex2f(h2.x - m);  A[5] = ex2f(h2.y - m);  A[6] = ex2f(h3.x - m);
            A[7] = ex2f(h3.y - m);  A[8] = ex2f(h4.x - m);  A[9] = ex2f(h4.y - m);
            A[10] = ex2f(h5.x - m); A[11] = ex2f(h5.y - m); A[12] = ex2f(h6.x - m);
            A[13] = ex2f(h6.y - m); A[14] = ex2f(h7.x - m); A[15] = ex2f(h7.y - m);
            A[16] = ex2f(h8.x - m); A[17] = ex2f(h8.y - m);

            #pragma unroll
            for (int jj = 0; jj < 8; ++jj) {
                if (8 * p + 1 + jj < Tn) {
                    int sl = s0 + jj; if (sl >= RING) sl -= RING;
                    const float* rg = ring[sl];
                    const float vb = rg[Cn - 1] + EPSF;
                    #pragma unroll
                    for (int q = 8; q >= 1; --q) {
                        if (q >= jj + 1) {
                            const float v = rg[vo[q-1]] + EPSF;
                            A[2*q+1] = fmaf(sk[q-1], A[2*q-1], A[2*q+1] + A[2*q]) * v;
                            A[2*q]   = (A[2*q] + A[2*q-1]) * vb;
                        }
                    }
                    if (k == 127) histL[8*p + 1 + jj] = A[17];
                }
            }
            if (k == 127) histM[p] = m;
            const float L16 = fmaxf(m + lg2f(A[16]), NEGF);
            const float L17 = fmaxf(m + lg2f(A[17]), NEGF);
            float2 w = { L16, L17 };
            *(float2*)&abuf[cur ^ 1][16 + 2 * k] = w;
        }
        else if (tid < 192) {              // loaders: rows 8p+17 .. 8p+24 (period p+2)
            const int lt = tid - 128;
            int sw = s0 + 16; if (sw >= RING) sw -= RING;
            #pragma unroll
            for (int rr = 0; rr < 8; ++rr) {
                const int rt = 8 * p + 17 + rr;
                if (rt < Tn) {
                    int sl = sw + rr; if (sl >= RING) sl -= RING;
                    unsigned sa = (unsigned)__cvta_generic_to_shared(&ring[sl][lt * 4]);
                    const float* g = rowbase + (size_t)rt * Cn + lt * 4;
                    asm volatile("cp.async.cg.shared.global [%0], [%1], 16;\n" :: "r"(sa), "l"(g));
                }
            }
            asm volatile("cp.async.commit_group;\n");
            asm volatile("cp.async.wait_group 1;\n");
        }
        else {                             // sums warps: w6 rows jj=0..3, w7 rows jj=4..7
            const int l = tid & 31;
            const int jb = (tid < 224) ? 0 : 4;
            float pr[4];
            #pragma unroll
            for (int rr = 0; rr < 4; ++rr) {
                const int t = 8 * p + 1 + jb + rr;
                if (t < Tn) {
                    int sl = s0 + jb + rr; if (sl >= RING) sl -= RING;
                    const float4* r4 = (const float4*)ring[sl];
                    float4 x = r4[l], y = r4[l + 32];
                    pr[rr] = ((x.x + x.y) + (x.z + x.w)) + ((y.x + y.y) + (y.z + y.w));
                    if (l == 31) vbh[t] = y.w;
                } else pr[rr] = 0.f;
            }
            #pragma unroll
            for (int o = 16; o; o >>= 1) {
                pr[0] += __shfl_xor_sync(0xffffffffu, pr[0], o);
                pr[1] += __shfl_xor_sync(0xffffffffu, pr[1], o);
                pr[2] += __shfl_xor_sync(0xffffffffu, pr[2], o);
                pr[3] += __shfl_xor_sync(0xffffffffu, pr[3], o);
            }
            if (l == 0) {
                #pragma unroll
                for (int rr = 0; rr < 4; ++rr) {
                    const int t = 8 * p + 1 + jb + rr;
                    if (t < Tn) sums[t] = pr[rr] + (float)Cn * EPSF;
                }
            }
        }
        __syncthreads();
        cur ^= 1;
        s0 += 8; if (s0 >= RING) s0 -= RING;
    }

    // ==== epilogue (A256 reconstruction + D), validated structure from R4/R5 ====
    if (tid < 128) {
        const int base = 8 * tid;
        float r = 0.f;
        #pragma unroll
        for (int j = 0; j < 8; ++j) {
            const int u = base + j;
            float x = (u == 0) ? 0.f : lg2f(vbh[u] + EPSF);
            r += x;
            pre[u] = r;
        }
        csum[tid] = r;
    }
    __syncthreads();

    if (tid < 32) {
        float c0 = csum[4*tid], c1 = csum[4*tid+1], c2 = csum[4*tid+2], c3 = csum[4*tid+3];
        float tot = ((c0 + c1) + (c2 + c3));
        float sc = tot;
        #pragma unroll
        for (int o = 1; o < 32; o <<= 1) {
            float v = __shfl_up_sync(0xffffffffu, sc, o);
            if (tid >= o) sc += v;
        }
        const float ex = sc - tot;
        coff[4*tid]   = ex;
        coff[4*tid+1] = ex + c0;
        coff[4*tid+2] = ex + c0 + c1;
        coff[4*tid+3] = ex + c0 + c1 + c2;
        if (tid == 31) PtotS = sc;
    }
    __syncthreads();

    const float Ptot = PtotS;
    float lm = -3.0e38f;
    for (int u = tid; u < Tn - 1; u += NTH) {
        const float h = (u == 0) ? NEGF : histM[(u - 1) >> 3] + lg2f(histL[u]);
        lm = fmaxf(lm, h + (Ptot - (coff[u >> 3] + pre[u])));
    }
    float d2 = 0.f;
    #pragma unroll
    for (int j = 0; j < Tn / NTH; ++j) d2 += lg2f(sums[tid + NTH * j]);
    #pragma unroll
    for (int o = 16; o; o >>= 1) {
        lm = fmaxf(lm, __shfl_xor_sync(0xffffffffu, lm, o));
        d2 += __shfl_xor_sync(0xffffffffu, d2, o);
    }
    if ((tid & 31) == 0) { wredA[tid >> 5] = lm; wredB[tid >> 5] = d2; }
    __syncthreads();

    float M = wredA[0];
    #pragma unroll
    for (int w = 1; w < 8; ++w) M = fmaxf(M, wredA[w]);

    float se = 0.f;
    for (int u = tid; u < Tn - 1; u += NTH) {
        const float h = (u == 0) ? NEGF : histM[(u - 1) >> 3] + lg2f(histL[u]);
        se += ex2f(h + (Ptot - (coff[u >> 3] + pre[u])) - M);
    }
    #pragma unroll
    for (int o = 16; o; o >>= 1) se += __shfl_xor_sync(0xffffffffu, se, o);
    if ((tid & 31) == 0) wredC[tid >> 5] = se;
    __syncthreads();

    if (tid == 0) {
        float S = 0.f, D2 = 0.f;
        #pragma unroll
        for (int w = 0; w < 8; ++w) { S += wredC[w]; D2 += wredB[w]; }
        const float a256 = M + lg2f(S);              // A256(T-1), base-2
        const float x = abuf[cur][16 + 255];         // A255(T-1), base-2
        const float m2 = fmaxf(x, a256);
        const float lse2 = m2 + lg2f(ex2f(x - m2) + ex2f(a256 - m2));
        out[b] = LN2F * (D2 - lse2);
    }
}

extern "C" void kernel_launch(void* const* d_in, const int* in_sizes, int n_in,
                              void* d_out, int out_size)
{
    int iy = (in_sizes[0] == Bn * Ln) ? 0 : 1;
    const void*  yt = d_in[iy];
    const float* yp = (const float*)d_in[1 - iy];
    ctc_kernel<<<Bn, NTH>>>(yt, yp, (float*)d_out);
}